// round 1
// baseline (speedup 1.0000x reference)
#include <cuda_runtime.h>
#include <math.h>
#include <stdint.h>

// ---------------- problem constants ----------------
#define TOK   4096          // B*N tokens
#define DIMM  2048
#define FUSED 18688
#define FFI   8192
#define NSEQ  2048
#define DH    128
#define QB    32            // NSEQ/64 query tiles

// ---------------- scratch (device globals: no allocation allowed) ----------
static __device__ float g_h[(size_t)TOK * DIMM];       //  32 MB  LN output
static __device__ float g_proj[(size_t)TOK * FUSED];   // 306 MB  fused projection
static __device__ float g_attn[(size_t)TOK * DIMM];    //  32 MB  attention concat
static __device__ float g_act[(size_t)TOK * FFI];      // 128 MB  swiglu activation
static __device__ float g_cos[NSEQ * 64];
static __device__ float g_sin[NSEQ * 64];

// ---------------- LayerNorm ----------------
__global__ __launch_bounds__(256) void ln_kernel(const float* __restrict__ x,
                                                 const float* __restrict__ gamma,
                                                 const float* __restrict__ beta,
                                                 float* __restrict__ h) {
    int row = blockIdx.x;
    int tid = threadIdx.x;
    const float* xr = x + (size_t)row * DIMM;
    float v[8];
    float s = 0.f, s2 = 0.f;
#pragma unroll
    for (int i = 0; i < 8; i++) {
        float t = xr[tid + i * 256];
        v[i] = t; s += t; s2 += t * t;
    }
#pragma unroll
    for (int o = 16; o > 0; o >>= 1) {
        s  += __shfl_xor_sync(0xffffffffu, s,  o);
        s2 += __shfl_xor_sync(0xffffffffu, s2, o);
    }
    __shared__ float rs[8], rs2[8];
    int w = tid >> 5, l = tid & 31;
    if (l == 0) { rs[w] = s; rs2[w] = s2; }
    __syncthreads();
    float S = 0.f, S2 = 0.f;
#pragma unroll
    for (int i = 0; i < 8; i++) { S += rs[i]; S2 += rs2[i]; }
    float mean = S * (1.f / DIMM);
    float var  = S2 * (1.f / DIMM) - mean * mean;
    float r = rsqrtf(var + 1e-5f);
    float* hr = h + (size_t)row * DIMM;
#pragma unroll
    for (int i = 0; i < 8; i++) {
        int c = tid + i * 256;
        hr[c] = (v[i] - mean) * r * gamma[c] + beta[c];
    }
}

// ---------------- tf32 helpers ----------------
__device__ __forceinline__ unsigned f2tf(float x) {
    unsigned u;
    asm("cvt.rna.tf32.f32 %0, %1;" : "=r"(u) : "f"(x));
    return u;
}
__device__ __forceinline__ void mma8(float* c, unsigned a0, unsigned a1, unsigned a2,
                                     unsigned a3, unsigned b0, unsigned b1) {
    asm volatile(
        "mma.sync.aligned.m16n8k8.row.col.f32.tf32.tf32.f32 "
        "{%0,%1,%2,%3}, {%4,%5,%6,%7}, {%8,%9}, {%0,%1,%2,%3};"
        : "+f"(c[0]), "+f"(c[1]), "+f"(c[2]), "+f"(c[3])
        : "r"(a0), "r"(a1), "r"(a2), "r"(a3), "r"(b0), "r"(b1));
}

// ---------------- 3xTF32 GEMM: C[M,N] (=|+=) A[M,K] * B[K,N], row-major ------
// block tile 128x128, K-tile 32, 8 warps (2x4), warp tile 64x32.
__global__ __launch_bounds__(256, 1) void gemm3_kernel(const float* __restrict__ A,
                                                       const float* __restrict__ B,
                                                       float* __restrict__ C,
                                                       int M, int N, int K, int accum) {
    __shared__ float As[32][132];  // [k][m]  (transposed on load)
    __shared__ float Bs[32][132];  // [k][n]
    int tid = threadIdx.x, lane = tid & 31, warp = tid >> 5;
    int g = lane >> 2, tig = lane & 3;
    int bm = blockIdx.y << 7, bn = blockIdx.x << 7;
    int wm = (warp >> 2) << 6, wn = (warp & 3) << 5;

    float acc[4][4][4];
#pragma unroll
    for (int mt = 0; mt < 4; mt++)
#pragma unroll
        for (int nt = 0; nt < 4; nt++)
#pragma unroll
            for (int r = 0; r < 4; r++) acc[mt][nt][r] = 0.f;

    for (int kb = 0; kb < K; kb += 32) {
        __syncthreads();
#pragma unroll
        for (int i = 0; i < 4; i++) {
            int f = tid + (i << 8);
            int m = f >> 3, k4 = (f & 7) << 2;
            float4 va = *(const float4*)(A + (size_t)(bm + m) * K + kb + k4);
            As[k4 + 0][m] = va.x;
            As[k4 + 1][m] = va.y;
            As[k4 + 2][m] = va.z;
            As[k4 + 3][m] = va.w;
            int k = f >> 5, n4 = (f & 31) << 2;
            *(float4*)&Bs[k][n4] = *(const float4*)(B + (size_t)(kb + k) * N + bn + n4);
        }
        __syncthreads();
#pragma unroll
        for (int kk = 0; kk < 32; kk += 8) {
            unsigned ah[4][4], al[4][4], bh[4][2], bl[4][2];
#pragma unroll
            for (int mt = 0; mt < 4; mt++) {
                int m0 = wm + (mt << 4) + g;
                float x0 = As[kk + tig][m0];
                float x1 = As[kk + tig][m0 + 8];
                float x2 = As[kk + tig + 4][m0];
                float x3 = As[kk + tig + 4][m0 + 8];
                ah[mt][0] = f2tf(x0); al[mt][0] = f2tf(x0 - __uint_as_float(ah[mt][0]));
                ah[mt][1] = f2tf(x1); al[mt][1] = f2tf(x1 - __uint_as_float(ah[mt][1]));
                ah[mt][2] = f2tf(x2); al[mt][2] = f2tf(x2 - __uint_as_float(ah[mt][2]));
                ah[mt][3] = f2tf(x3); al[mt][3] = f2tf(x3 - __uint_as_float(ah[mt][3]));
            }
#pragma unroll
            for (int nt = 0; nt < 4; nt++) {
                int n0 = wn + (nt << 3) + g;
                float y0 = Bs[kk + tig][n0];
                float y1 = Bs[kk + tig + 4][n0];
                bh[nt][0] = f2tf(y0); bl[nt][0] = f2tf(y0 - __uint_as_float(bh[nt][0]));
                bh[nt][1] = f2tf(y1); bl[nt][1] = f2tf(y1 - __uint_as_float(bh[nt][1]));
            }
#pragma unroll
            for (int mt = 0; mt < 4; mt++)
#pragma unroll
                for (int nt = 0; nt < 4; nt++) {
                    mma8(acc[mt][nt], ah[mt][0], ah[mt][1], ah[mt][2], ah[mt][3],
                         bh[nt][0], bh[nt][1]);
                    mma8(acc[mt][nt], al[mt][0], al[mt][1], al[mt][2], al[mt][3],
                         bh[nt][0], bh[nt][1]);
                    mma8(acc[mt][nt], ah[mt][0], ah[mt][1], ah[mt][2], ah[mt][3],
                         bl[nt][0], bl[nt][1]);
                }
        }
    }
    // epilogue
#pragma unroll
    for (int mt = 0; mt < 4; mt++) {
        int r0 = bm + wm + (mt << 4) + g;
#pragma unroll
        for (int nt = 0; nt < 4; nt++) {
            int c0 = bn + wn + (nt << 3) + (tig << 1);
            float* p0 = C + (size_t)r0 * N + c0;
            float* p1 = C + (size_t)(r0 + 8) * N + c0;
            if (accum) {
                p0[0] += acc[mt][nt][0];
                p0[1] += acc[mt][nt][1];
                p1[0] += acc[mt][nt][2];
                p1[1] += acc[mt][nt][3];
            } else {
                p0[0] = acc[mt][nt][0];
                p0[1] = acc[mt][nt][1];
                p1[0] = acc[mt][nt][2];
                p1[1] = acc[mt][nt][3];
            }
        }
    }
}

// ---------------- RoPE tables + apply ----------------
__global__ void rope_table_kernel() {
    int idx = blockIdx.x * blockDim.x + threadIdx.x;
    if (idx >= NSEQ * 64) return;
    int n = idx >> 6, i = idx & 63;
    double invf = pow(10000.0, -(double)i / 64.0);
    double th = (double)n * invf;
    g_cos[idx] = (float)cos(th);
    g_sin[idx] = (float)sin(th);
}

__global__ void rope_kernel() {
    int idx = blockIdx.x * blockDim.x + threadIdx.x;
    if (idx >= TOK * 17 * 64) return;
    int i = idx & 63;
    int t = idx >> 6;
    int head = t % 17;          // heads 0..15 = q, 16 = k
    int row = t / 17;
    int pos = row & (NSEQ - 1);
    float c = g_cos[(pos << 6) + i];
    float s = g_sin[(pos << 6) + i];
    size_t base = (size_t)row * FUSED + (head < 16 ? (head << 7) : 2048);
    float v0 = g_proj[base + i];
    float v1 = g_proj[base + i + 64];
    g_proj[base + i]      = v0 * c - v1 * s;
    g_proj[base + i + 64] = v1 * c + v0 * s;
}

// ---------------- fp32 flash attention (MQA, causal) ----------------
// grid (32 q-tiles, 16 heads, 2 batch), 256 threads; thread = (row=tid/4, part=tid%4)
#define ATTN_SMEM ((3 * 64 * 132 + 64 * 68) * 4)

__global__ __launch_bounds__(256, 1) void attn_kernel() {
    extern __shared__ float sm[];
    float* Qs = sm;                  // [64][132]
    float* Ks = sm + 64 * 132;       // [64][132]
    float* Vs = sm + 2 * 64 * 132;   // [64][132]
    float* Ps = sm + 3 * 64 * 132;   // [64][68]
    int tid = threadIdx.x;
    int qb = blockIdx.x, hh = blockIdx.y, bb = blockIdx.z;
    int row = tid >> 2, part = tid & 3;
    size_t rowbase = (size_t)(bb * NSEQ) * FUSED;

#pragma unroll
    for (int i = 0; i < 8; i++) {       // load Q tile (64x128)
        int f = tid + (i << 8);
        int r = f >> 5, c4 = (f & 31) << 2;
        *(float4*)&Qs[r * 132 + c4] =
            *(const float4*)(g_proj + rowbase + (size_t)(qb * 64 + r) * FUSED + hh * DH + c4);
    }

    float m_i = -1e30f, l_i = 0.f;
    float4 Oa[8];
#pragma unroll
    for (int j = 0; j < 8; j++) Oa[j] = make_float4(0.f, 0.f, 0.f, 0.f);
    const float scale = 0.08838834764831845f;  // 1/sqrt(128)
    int qg = qb * 64 + row;

    for (int kb = 0; kb <= qb; kb++) {
        __syncthreads();  // previous tile's Vs/Ks fully consumed
#pragma unroll
        for (int i = 0; i < 8; i++) {   // load K,V tiles (64x128 each)
            int f = tid + (i << 8);
            int r = f >> 5, c4 = (f & 31) << 2;
            size_t src = rowbase + (size_t)(kb * 64 + r) * FUSED;
            *(float4*)&Ks[r * 132 + c4] = *(const float4*)(g_proj + src + 2048 + c4);
            *(float4*)&Vs[r * 132 + c4] = *(const float4*)(g_proj + src + 2176 + c4);
        }
        __syncthreads();

        float S[16];
#pragma unroll
        for (int j = 0; j < 16; j++) S[j] = 0.f;
#pragma unroll 4
        for (int k4 = 0; k4 < 128; k4 += 4) {
            float4 q = *(float4*)&Qs[row * 132 + k4];
#pragma unroll
            for (int j = 0; j < 16; j++) {  // thread's cols: c = part + 4*j (interleaved)
                float4 kv = *(float4*)&Ks[(part + (j << 2)) * 132 + k4];
                S[j] += q.x * kv.x + q.y * kv.y + q.z * kv.z + q.w * kv.w;
            }
        }
        float mx = -1e30f;
#pragma unroll
        for (int j = 0; j < 16; j++) {
            int kg = kb * 64 + part + (j << 2);
            S[j] = (kg <= qg) ? S[j] * scale : -1e30f;
            mx = fmaxf(mx, S[j]);
        }
        mx = fmaxf(mx, __shfl_xor_sync(0xffffffffu, mx, 1));
        mx = fmaxf(mx, __shfl_xor_sync(0xffffffffu, mx, 2));
        float m_new = fmaxf(m_i, mx);
        float alpha = __expf(m_i - m_new);
        float ps = 0.f;
#pragma unroll
        for (int j = 0; j < 16; j++) {
            float p = __expf(S[j] - m_new);
            S[j] = p; ps += p;
        }
        ps += __shfl_xor_sync(0xffffffffu, ps, 1);
        ps += __shfl_xor_sync(0xffffffffu, ps, 2);
        l_i = l_i * alpha + ps;
        m_i = m_new;
#pragma unroll
        for (int j = 0; j < 8; j++) {
            Oa[j].x *= alpha; Oa[j].y *= alpha; Oa[j].z *= alpha; Oa[j].w *= alpha;
        }
#pragma unroll
        for (int j = 0; j < 16; j++) Ps[row * 68 + part + (j << 2)] = S[j];
        __syncwarp();  // Ps row shared only within the quad (same warp)
#pragma unroll 4
        for (int c = 0; c < 64; c++) {
            float p = Ps[row * 68 + c];
            const float4* vr = (const float4*)&Vs[c * 132];
#pragma unroll
            for (int j = 0; j < 8; j++) {   // thread's f4 chunks: part + 4*j
                float4 v = vr[part + (j << 2)];
                Oa[j].x += p * v.x; Oa[j].y += p * v.y;
                Oa[j].z += p * v.z; Oa[j].w += p * v.w;
            }
        }
    }
    float inv = 1.f / l_i;
    float* op = g_attn + (size_t)(bb * NSEQ + qb * 64 + row) * DIMM + hh * DH;
#pragma unroll
    for (int j = 0; j < 8; j++) {
        int d = (part + (j << 2)) << 2;
        float4 o;
        o.x = Oa[j].x * inv; o.y = Oa[j].y * inv;
        o.z = Oa[j].z * inv; o.w = Oa[j].w * inv;
        *(float4*)&op[d] = o;
    }
}

// ---------------- SwiGLU ----------------
__global__ __launch_bounds__(256) void swiglu_kernel() {
    int idx = blockIdx.x * blockDim.x + threadIdx.x;  // per float4
    if (idx >= TOK * (FFI / 4)) return;
    int row = idx / (FFI / 4);
    int c4 = (idx % (FFI / 4)) << 2;
    const float4 xv = *(const float4*)(g_proj + (size_t)row * FUSED + 2304 + c4);
    const float4 gv = *(const float4*)(g_proj + (size_t)row * FUSED + 2304 + FFI + c4);
    float4 o;
    o.x = xv.x * gv.x / (1.f + __expf(-gv.x));
    o.y = xv.y * gv.y / (1.f + __expf(-gv.y));
    o.z = xv.z * gv.z / (1.f + __expf(-gv.z));
    o.w = xv.w * gv.w / (1.f + __expf(-gv.w));
    *(float4*)(g_act + (size_t)row * FFI + c4) = o;
}

// ---------------- launch ----------------
extern "C" void kernel_launch(void* const* d_in, const int* in_sizes, int n_in,
                              void* d_out, int out_size) {
    (void)in_sizes; (void)n_in; (void)out_size;
    const float* x     = (const float*)d_in[0];
    const float* gamma = (const float*)d_in[1];
    const float* beta  = (const float*)d_in[2];
    const float* wf    = (const float*)d_in[3];
    const float* wao   = (const float*)d_in[4];
    const float* wfo   = (const float*)d_in[5];
    float* out = (float*)d_out;

    float *ph, *pproj, *pattn, *pact;
    cudaGetSymbolAddress((void**)&ph, g_h);
    cudaGetSymbolAddress((void**)&pproj, g_proj);
    cudaGetSymbolAddress((void**)&pattn, g_attn);
    cudaGetSymbolAddress((void**)&pact, g_act);

    cudaFuncSetAttribute(attn_kernel, cudaFuncAttributeMaxDynamicSharedMemorySize,
                         ATTN_SMEM);

    // 1. LayerNorm
    ln_kernel<<<TOK, 256>>>(x, gamma, beta, ph);
    // 2. fused projection: [4096,2048] @ [2048,18688]
    gemm3_kernel<<<dim3(FUSED / 128, TOK / 128), 256>>>(ph, wf, pproj, TOK, FUSED, DIMM, 0);
    // 3. RoPE
    rope_table_kernel<<<(NSEQ * 64 + 255) / 256, 256>>>();
    rope_kernel<<<(TOK * 17 * 64 + 255) / 256, 256>>>();
    // 4. causal MQA attention
    attn_kernel<<<dim3(QB, 16, 2), 256, ATTN_SMEM>>>();
    // 5. SwiGLU
    swiglu_kernel<<<(TOK * (FFI / 4) + 255) / 256, 256>>>();
    // 6. ff output GEMM (writes out), then attn output GEMM (accumulates)
    gemm3_kernel<<<dim3(DIMM / 128, TOK / 128), 256>>>(pact, wfo, out, TOK, DIMM, FFI, 0);
    gemm3_kernel<<<dim3(DIMM / 128, TOK / 128), 256>>>(pattn, wao, out, TOK, DIMM, DIMM, 1);
}

// round 7
// speedup vs baseline: 1.4184x; 1.4184x over previous
#include <cuda_runtime.h>
#include <cuda_bf16.h>
#include <math.h>
#include <stdint.h>

// ---------------- problem constants ----------------
#define TOK   4096          // B*N tokens
#define DIMM  2048
#define FUSED 18688
#define FFI   8192
#define NSEQ  2048
#define DH    128
#define K2    10240         // FFI + ATTN_INNER for combined output GEMM
#define QB    32

// ---------------- scratch (device globals) ----------------
static __device__ float g_proj[(size_t)TOK * FUSED];                  // 306 MB
static __device__ __nv_bfloat16 g_hh[(size_t)TOK * DIMM];             // LN out hi
static __device__ __nv_bfloat16 g_hl[(size_t)TOK * DIMM];             // LN out lo
static __device__ __nv_bfloat16 g_wfTh[(size_t)FUSED * DIMM];         // wf^T hi
static __device__ __nv_bfloat16 g_wfTl[(size_t)FUSED * DIMM];
static __device__ __nv_bfloat16 g_w2Th[(size_t)DIMM * K2];            // [wfo;wao]^T hi
static __device__ __nv_bfloat16 g_w2Tl[(size_t)DIMM * K2];
static __device__ __nv_bfloat16 g_a2h[(size_t)TOK * K2];              // [act|attn] hi
static __device__ __nv_bfloat16 g_a2l[(size_t)TOK * K2];
static __device__ float g_cos[NSEQ * 64];
static __device__ float g_sin[NSEQ * 64];

// ---------------- PTX helpers (arch-generic, sm_80-level) ----------------
__device__ __forceinline__ uint32_t s2u(const void* p) {
    uint32_t a;
    asm("{ .reg .u64 t; cvta.to.shared.u64 t, %1; cvt.u32.u64 %0, t; }"
        : "=r"(a) : "l"(p));
    return a;
}
__device__ __forceinline__ void cpa16(uint32_t dst, const void* src) {
    asm volatile("cp.async.cg.shared.global [%0], [%1], 16;" :: "r"(dst), "l"(src));
}
__device__ __forceinline__ void cpa_commit() {
    asm volatile("cp.async.commit_group;");
}
template <int N>
__device__ __forceinline__ void cpa_wait() {
    asm volatile("cp.async.wait_group %0;" :: "n"(N));
}
__device__ __forceinline__ void ldsm4(uint32_t* r, uint32_t addr) {
    asm volatile("ldmatrix.sync.aligned.m8n8.x4.shared.b16 {%0,%1,%2,%3}, [%4];"
                 : "=r"(r[0]), "=r"(r[1]), "=r"(r[2]), "=r"(r[3]) : "r"(addr));
}
__device__ __forceinline__ void mma16816(float* c, const uint32_t* a,
                                         const uint32_t* b) {
    asm volatile(
        "mma.sync.aligned.m16n8k16.row.col.f32.bf16.bf16.f32 "
        "{%0,%1,%2,%3}, {%4,%5,%6,%7}, {%8,%9}, {%0,%1,%2,%3};"
        : "+f"(c[0]), "+f"(c[1]), "+f"(c[2]), "+f"(c[3])
        : "r"(a[0]), "r"(a[1]), "r"(a[2]), "r"(a[3]), "r"(b[0]), "r"(b[1]));
}

// ---------------- bf16 3-pass GEMM on mma.sync ----------------
// C[M,N] = (Ah+Al)[M,K] * (Bh+Bl)[N,K]^T, fp32 accum; error ~2^-16.
// 128x128 CTA tile, K-chunk 64, 2-stage cp.async double buffer, ldmatrix feeds.
// smem tile layout: row r (128B) with 16B granule c stored at (c ^ (r&7)).
#define BGE_SMEM (8 * 16384)   // 2 stages x {Ah,Al,Bh,Bl} x 16KB = 128KB

__device__ __forceinline__ void bge_load_chunk(const __nv_bfloat16* src, int rbase,
                                               int K, int chunk, int s, int t, int u,
                                               uint32_t sb) {
    int kb = chunk << 6;
#pragma unroll
    for (int rr = 0; rr < 2; rr++) {
        int r = u + (rr << 6);
        const char* g = (const char*)(src + (size_t)(rbase + r) * K + kb);
        uint32_t d0 = sb + (uint32_t)(((s << 2) + t) << 14) + (uint32_t)(r << 7);
        int x = r & 7;
#pragma unroll
        for (int c = 0; c < 8; c++) cpa16(d0 + (uint32_t)((c ^ x) << 4), g + (c << 4));
    }
    cpa_commit();
}

__global__ __launch_bounds__(256, 1) void bf_gemm(
    const __nv_bfloat16* __restrict__ Ah, const __nv_bfloat16* __restrict__ Al,
    const __nv_bfloat16* __restrict__ Bh, const __nv_bfloat16* __restrict__ Bl,
    float* __restrict__ C, int M, int N, int K) {
    extern __shared__ __align__(128) char smem[];
    uint32_t sb = s2u(smem);
    int tid = threadIdx.x, lane = tid & 31, warp = tid >> 5;
    int bm = blockIdx.x << 7, bn = blockIdx.y << 7;   // x = M (fast) => B-panel L2 reuse
    int wm = (warp >> 2) << 6, wn = (warp & 3) << 5;  // warp tile 64x32

    // loader role: tile t in {Ah,Al,Bh,Bl}, 64 threads each, 2 rows/thread
    int t = tid >> 6, u = tid & 63;
    const __nv_bfloat16* src = (t == 0) ? Ah : (t == 1) ? Al : (t == 2) ? Bh : Bl;
    int rbase = (t < 2) ? bm : bn;
    int nk = K >> 6;

    float acc[4][4][4];
#pragma unroll
    for (int mt = 0; mt < 4; mt++)
#pragma unroll
        for (int nt = 0; nt < 4; nt++)
#pragma unroll
            for (int e = 0; e < 4; e++) acc[mt][nt][e] = 0.f;

    bge_load_chunk(src, rbase, K, 0, 0, t, u, sb);
    bge_load_chunk(src, rbase, K, 1, 1, t, u, sb);

    // per-thread ldmatrix row/granule components
    uint32_t a_row = (uint32_t)(wm + (lane & 15)) << 7;
    uint32_t b_row = (uint32_t)(wn + (lane & 7) + ((lane >> 4) << 3)) << 7;
    int ga = lane >> 4;          // A granule low bit
    int gb = (lane >> 3) & 1;    // B granule low bit
    int lx = lane & 7;

    for (int i = 0; i < nk; i++) {
        int s = i & 1;
        if (i + 1 < nk) cpa_wait<1>(); else cpa_wait<0>();
        __syncthreads();
        uint32_t base = sb + (uint32_t)((s << 2) << 14);
        uint32_t Ahb = base, Alb = base + 16384;
        uint32_t Bhb = base + 32768, Blb = base + 49152;
#pragma unroll
        for (int kk = 0; kk < 4; kk++) {
            uint32_t xga = (uint32_t)((((kk << 1) + ga) ^ lx)) << 4;
            uint32_t xgb = (uint32_t)((((kk << 1) + gb) ^ lx)) << 4;
            uint32_t ahf[4][4], alf[4][4], bhf[2][4], blf[2][4];
#pragma unroll
            for (int mt = 0; mt < 4; mt++) {
                ldsm4(ahf[mt], Ahb + a_row + (mt << 11) + xga);
                ldsm4(alf[mt], Alb + a_row + (mt << 11) + xga);
            }
#pragma unroll
            for (int nt = 0; nt < 2; nt++) {
                ldsm4(bhf[nt], Bhb + b_row + (nt << 11) + xgb);
                ldsm4(blf[nt], Blb + b_row + (nt << 11) + xgb);
            }
#pragma unroll
            for (int mt = 0; mt < 4; mt++)
#pragma unroll
                for (int nt = 0; nt < 4; nt++) {
                    const uint32_t* bh2 = &bhf[nt >> 1][(nt & 1) << 1];
                    const uint32_t* bl2 = &blf[nt >> 1][(nt & 1) << 1];
                    mma16816(acc[mt][nt], ahf[mt], bh2);  // hi*hi
                    mma16816(acc[mt][nt], alf[mt], bh2);  // lo*hi
                    mma16816(acc[mt][nt], ahf[mt], bl2);  // hi*lo
                }
        }
        __syncthreads();
        if (i + 2 < nk) bge_load_chunk(src, rbase, K, i + 2, s, t, u, sb);
    }

    // epilogue
    int r0 = bm + wm + (lane >> 2);
    int c0 = bn + wn + ((lane & 3) << 1);
#pragma unroll
    for (int mt = 0; mt < 4; mt++)
#pragma unroll
        for (int nt = 0; nt < 4; nt++) {
            float2 v0 = make_float2(acc[mt][nt][0], acc[mt][nt][1]);
            float2 v1 = make_float2(acc[mt][nt][2], acc[mt][nt][3]);
            *(float2*)&C[(size_t)(r0 + (mt << 4)) * N + c0 + (nt << 3)] = v0;
            *(float2*)&C[(size_t)(r0 + (mt << 4) + 8) * N + c0 + (nt << 3)] = v1;
        }
}

// ---------------- transpose + fp32 -> bf16 hi/lo split ----------------
__global__ __launch_bounds__(256) void transpose_conv(const float* __restrict__ in,
                                                      int R, int C,
                                                      __nv_bfloat16* __restrict__ oh,
                                                      __nv_bfloat16* __restrict__ ol,
                                                      int ldo, int coff) {
    __shared__ float tbuf[32][33];
    int bc = blockIdx.x << 5, br = blockIdx.y << 5;
    int tx = threadIdx.x & 31, ty = threadIdx.x >> 5;
#pragma unroll
    for (int i = 0; i < 32; i += 8)
        tbuf[ty + i][tx] = in[(size_t)(br + ty + i) * C + bc + tx];
    __syncthreads();
#pragma unroll
    for (int i = 0; i < 32; i += 8) {
        float v = tbuf[tx][ty + i];
        __nv_bfloat16 hi = __float2bfloat16(v);
        __nv_bfloat16 lo = __float2bfloat16(v - __bfloat162float(hi));
        size_t o = (size_t)(bc + ty + i) * ldo + coff + br + tx;
        oh[o] = hi;
        ol[o] = lo;
    }
}

// ---------------- LayerNorm -> bf16 hi/lo ----------------
__global__ __launch_bounds__(256) void ln_kernel(const float* __restrict__ x,
                                                 const float* __restrict__ gamma,
                                                 const float* __restrict__ beta) {
    int row = blockIdx.x;
    int tid = threadIdx.x;
    const float* xr = x + (size_t)row * DIMM;
    float v[8];
    float s = 0.f, s2 = 0.f;
#pragma unroll
    for (int i = 0; i < 8; i++) {
        float tv = xr[tid + i * 256];
        v[i] = tv; s += tv; s2 += tv * tv;
    }
#pragma unroll
    for (int o = 16; o > 0; o >>= 1) {
        s  += __shfl_xor_sync(0xffffffffu, s,  o);
        s2 += __shfl_xor_sync(0xffffffffu, s2, o);
    }
    __shared__ float rs[8], rs2[8];
    int w = tid >> 5, l = tid & 31;
    if (l == 0) { rs[w] = s; rs2[w] = s2; }
    __syncthreads();
    float S = 0.f, S2 = 0.f;
#pragma unroll
    for (int i = 0; i < 8; i++) { S += rs[i]; S2 += rs2[i]; }
    float mean = S * (1.f / DIMM);
    float var  = S2 * (1.f / DIMM) - mean * mean;
    float r = rsqrtf(var + 1e-5f);
    __nv_bfloat16* hh = g_hh + (size_t)row * DIMM;
    __nv_bfloat16* hl = g_hl + (size_t)row * DIMM;
#pragma unroll
    for (int i = 0; i < 8; i++) {
        int c = tid + i * 256;
        float y = (v[i] - mean) * r * gamma[c] + beta[c];
        __nv_bfloat16 hi = __float2bfloat16(y);
        hh[c] = hi;
        hl[c] = __float2bfloat16(y - __bfloat162float(hi));
    }
}

// ---------------- RoPE ----------------
__global__ void rope_table_kernel() {
    int idx = blockIdx.x * blockDim.x + threadIdx.x;
    if (idx >= NSEQ * 64) return;
    int n = idx >> 6, i = idx & 63;
    double invf = pow(10000.0, -(double)i / 64.0);
    double th = (double)n * invf;
    g_cos[idx] = (float)cos(th);
    g_sin[idx] = (float)sin(th);
}

__global__ void rope_kernel() {
    int idx = blockIdx.x * blockDim.x + threadIdx.x;
    if (idx >= TOK * 17 * 64) return;
    int i = idx & 63;
    int t = idx >> 6;
    int head = t % 17;          // heads 0..15 = q, 16 = k
    int row = t / 17;
    int pos = row & (NSEQ - 1);
    float c = g_cos[(pos << 6) + i];
    float s = g_sin[(pos << 6) + i];
    size_t base = (size_t)row * FUSED + (head < 16 ? (head << 7) : 2048);
    float v0 = g_proj[base + i];
    float v1 = g_proj[base + i + 64];
    g_proj[base + i]      = v0 * c - v1 * s;
    g_proj[base + i + 64] = v1 * c + v0 * s;
}

// ---------------- fp32 flash attention (MQA, causal) -> bf16 hi/lo into a2 ----
#define ATTN_SMEM ((3 * 64 * 132 + 64 * 68) * 4)

__global__ __launch_bounds__(256, 1) void attn_kernel() {
    extern __shared__ float sm[];
    float* Qs = sm;                  // [64][132]
    float* Ks = sm + 64 * 132;
    float* Vs = sm + 2 * 64 * 132;
    float* Ps = sm + 3 * 64 * 132;   // [64][68]
    int tid = threadIdx.x;
    int qb = blockIdx.x, hh = blockIdx.y, bb = blockIdx.z;
    int row = tid >> 2, part = tid & 3;
    size_t rowbase = (size_t)(bb * NSEQ) * FUSED;

#pragma unroll
    for (int i = 0; i < 8; i++) {
        int f = tid + (i << 8);
        int r = f >> 5, c4 = (f & 31) << 2;
        *(float4*)&Qs[r * 132 + c4] =
            *(const float4*)(g_proj + rowbase + (size_t)(qb * 64 + r) * FUSED + hh * DH + c4);
    }

    float m_i = -1e30f, l_i = 0.f;
    float4 Oa[8];
#pragma unroll
    for (int j = 0; j < 8; j++) Oa[j] = make_float4(0.f, 0.f, 0.f, 0.f);
    const float scale = 0.08838834764831845f;
    int qg = qb * 64 + row;

    for (int kb = 0; kb <= qb; kb++) {
        __syncthreads();
#pragma unroll
        for (int i = 0; i < 8; i++) {
            int f = tid + (i << 8);
            int r = f >> 5, c4 = (f & 31) << 2;
            size_t src = rowbase + (size_t)(kb * 64 + r) * FUSED;
            *(float4*)&Ks[r * 132 + c4] = *(const float4*)(g_proj + src + 2048 + c4);
            *(float4*)&Vs[r * 132 + c4] = *(const float4*)(g_proj + src + 2176 + c4);
        }
        __syncthreads();

        float S[16];
#pragma unroll
        for (int j = 0; j < 16; j++) S[j] = 0.f;
#pragma unroll 4
        for (int k4 = 0; k4 < 128; k4 += 4) {
            float4 q = *(float4*)&Qs[row * 132 + k4];
#pragma unroll
            for (int j = 0; j < 16; j++) {
                float4 kv = *(float4*)&Ks[(part + (j << 2)) * 132 + k4];
                S[j] += q.x * kv.x + q.y * kv.y + q.z * kv.z + q.w * kv.w;
            }
        }
        float mx = -1e30f;
#pragma unroll
        for (int j = 0; j < 16; j++) {
            int kg = kb * 64 + part + (j << 2);
            S[j] = (kg <= qg) ? S[j] * scale : -1e30f;
            mx = fmaxf(mx, S[j]);
        }
        mx = fmaxf(mx, __shfl_xor_sync(0xffffffffu, mx, 1));
        mx = fmaxf(mx, __shfl_xor_sync(0xffffffffu, mx, 2));
        float m_new = fmaxf(m_i, mx);
        float alpha = __expf(m_i - m_new);
        float ps = 0.f;
#pragma unroll
        for (int j = 0; j < 16; j++) {
            float p = __expf(S[j] - m_new);
            S[j] = p; ps += p;
        }
        ps += __shfl_xor_sync(0xffffffffu, ps, 1);
        ps += __shfl_xor_sync(0xffffffffu, ps, 2);
        l_i = l_i * alpha + ps;
        m_i = m_new;
#pragma unroll
        for (int j = 0; j < 8; j++) {
            Oa[j].x *= alpha; Oa[j].y *= alpha; Oa[j].z *= alpha; Oa[j].w *= alpha;
        }
#pragma unroll
        for (int j = 0; j < 16; j++) Ps[row * 68 + part + (j << 2)] = S[j];
        __syncwarp();
#pragma unroll 4
        for (int c = 0; c < 64; c++) {
            float p = Ps[row * 68 + c];
            const float4* vr = (const float4*)&Vs[c * 132];
#pragma unroll
            for (int j = 0; j < 8; j++) {
                float4 v = vr[part + (j << 2)];
                Oa[j].x += p * v.x; Oa[j].y += p * v.y;
                Oa[j].z += p * v.z; Oa[j].w += p * v.w;
            }
        }
    }
    float inv = 1.f / l_i;
    size_t ob = (size_t)(bb * NSEQ + qb * 64 + row) * K2 + FFI + hh * DH;
#pragma unroll
    for (int j = 0; j < 8; j++) {
        int d = (part + (j << 2)) << 2;
        float vv[4] = {Oa[j].x * inv, Oa[j].y * inv, Oa[j].z * inv, Oa[j].w * inv};
#pragma unroll
        for (int e = 0; e < 4; e++) {
            __nv_bfloat16 hi = __float2bfloat16(vv[e]);
            g_a2h[ob + d + e] = hi;
            g_a2l[ob + d + e] = __float2bfloat16(vv[e] - __bfloat162float(hi));
        }
    }
}

// ---------------- SwiGLU -> bf16 hi/lo into a2 ----------------
__global__ __launch_bounds__(256) void swiglu_kernel() {
    int idx = blockIdx.x * blockDim.x + threadIdx.x;
    if (idx >= TOK * (FFI / 4)) return;
    int row = idx / (FFI / 4);
    int c4 = (idx % (FFI / 4)) << 2;
    const float4 xv = *(const float4*)(g_proj + (size_t)row * FUSED + 2304 + c4);
    const float4 gv = *(const float4*)(g_proj + (size_t)row * FUSED + 2304 + FFI + c4);
    float o[4];
    o[0] = xv.x * gv.x / (1.f + __expf(-gv.x));
    o[1] = xv.y * gv.y / (1.f + __expf(-gv.y));
    o[2] = xv.z * gv.z / (1.f + __expf(-gv.z));
    o[3] = xv.w * gv.w / (1.f + __expf(-gv.w));
    size_t ob = (size_t)row * K2 + c4;
#pragma unroll
    for (int e = 0; e < 4; e++) {
        __nv_bfloat16 hi = __float2bfloat16(o[e]);
        g_a2h[ob + e] = hi;
        g_a2l[ob + e] = __float2bfloat16(o[e] - __bfloat162float(hi));
    }
}

// ---------------- launch ----------------
extern "C" void kernel_launch(void* const* d_in, const int* in_sizes, int n_in,
                              void* d_out, int out_size) {
    (void)in_sizes; (void)n_in; (void)out_size;
    const float* x     = (const float*)d_in[0];
    const float* gamma = (const float*)d_in[1];
    const float* beta  = (const float*)d_in[2];
    const float* wf    = (const float*)d_in[3];
    const float* wao   = (const float*)d_in[4];
    const float* wfo   = (const float*)d_in[5];
    float* out = (float*)d_out;

    __nv_bfloat16 *phh, *phl, *pwfTh, *pwfTl, *pw2Th, *pw2Tl, *pa2h, *pa2l;
    float* pproj;
    cudaGetSymbolAddress((void**)&pproj, g_proj);
    cudaGetSymbolAddress((void**)&phh, g_hh);
    cudaGetSymbolAddress((void**)&phl, g_hl);
    cudaGetSymbolAddress((void**)&pwfTh, g_wfTh);
    cudaGetSymbolAddress((void**)&pwfTl, g_wfTl);
    cudaGetSymbolAddress((void**)&pw2Th, g_w2Th);
    cudaGetSymbolAddress((void**)&pw2Tl, g_w2Tl);
    cudaGetSymbolAddress((void**)&pa2h, g_a2h);
    cudaGetSymbolAddress((void**)&pa2l, g_a2l);

    cudaFuncSetAttribute(bf_gemm, cudaFuncAttributeMaxDynamicSharedMemorySize,
                         BGE_SMEM);
    cudaFuncSetAttribute(attn_kernel, cudaFuncAttributeMaxDynamicSharedMemorySize,
                         ATTN_SMEM);

    // weight conversions (transposed bf16 hi/lo)
    transpose_conv<<<dim3(FUSED / 32, DIMM / 32), 256>>>(wf, DIMM, FUSED,
                                                         pwfTh, pwfTl, DIMM, 0);
    transpose_conv<<<dim3(DIMM / 32, FFI / 32), 256>>>(wfo, FFI, DIMM,
                                                       pw2Th, pw2Tl, K2, 0);
    transpose_conv<<<dim3(DIMM / 32, DIMM / 32), 256>>>(wao, DIMM, DIMM,
                                                        pw2Th, pw2Tl, K2, FFI);
    // LayerNorm
    ln_kernel<<<TOK, 256>>>(x, gamma, beta);
    // fused projection GEMM: [4096,2048] x [18688,2048]^T -> g_proj
    bf_gemm<<<dim3(TOK / 128, FUSED / 128), 256, BGE_SMEM>>>(
        phh, phl, pwfTh, pwfTl, pproj, TOK, FUSED, DIMM);
    // RoPE
    rope_table_kernel<<<(NSEQ * 64 + 255) / 256, 256>>>();
    rope_kernel<<<(TOK * 17 * 64 + 255) / 256, 256>>>();
    // attention -> a2[:, 8192:]
    attn_kernel<<<dim3(QB, 16, 2), 256, ATTN_SMEM>>>();
    // swiglu -> a2[:, :8192]
    swiglu_kernel<<<(TOK * (FFI / 4) + 255) / 256, 256>>>();
    // combined output GEMM: [4096,10240] x [2048,10240]^T -> out
    bf_gemm<<<dim3(TOK / 128, DIMM / 128), 256, BGE_SMEM>>>(
        pa2h, pa2l, pw2Th, pw2Tl, out, TOK, DIMM, K2);
}

// round 10
// speedup vs baseline: 1.9013x; 1.3405x over previous
#include <cuda_runtime.h>
#include <cuda_fp16.h>
#include <math.h>
#include <stdint.h>

// ---------------- problem constants ----------------
#define TOK   4096          // B*N tokens
#define DIMM  2048
#define FUSED 18688
#define FFI   8192
#define NSEQ  2048
#define DH    128
#define K2    10240         // FFI + ATTN_INNER for combined output GEMM
#define QB    32

// ---------------- scratch (device globals) ----------------
static __device__ float g_proj[(size_t)TOK * FUSED];        // 306 MB
static __device__ __half g_hh[(size_t)TOK * DIMM];          // LN out hi
static __device__ __half g_hl[(size_t)TOK * DIMM];          // LN out lo
static __device__ __half g_wfTh[(size_t)FUSED * DIMM];      // wf^T hi (fp16)
static __device__ __half g_w2Th[(size_t)DIMM * K2];         // [wfo;wao]^T hi
static __device__ __half g_a2h[(size_t)TOK * K2];           // [act|attn] hi
static __device__ __half g_a2l[(size_t)TOK * K2];           // [act|attn] lo
static __device__ float g_cos[NSEQ * 64];
static __device__ float g_sin[NSEQ * 64];

// ---------------- PTX helpers (arch-generic, sm_80-level) ----------------
__device__ __forceinline__ uint32_t s2u(const void* p) {
    uint32_t a;
    asm("{ .reg .u64 t; cvta.to.shared.u64 t, %1; cvt.u32.u64 %0, t; }"
        : "=r"(a) : "l"(p));
    return a;
}
__device__ __forceinline__ void cpa16(uint32_t dst, const void* src) {
    asm volatile("cp.async.cg.shared.global [%0], [%1], 16;" :: "r"(dst), "l"(src));
}
__device__ __forceinline__ void cpa_commit() {
    asm volatile("cp.async.commit_group;");
}
template <int N>
__device__ __forceinline__ void cpa_wait() {
    asm volatile("cp.async.wait_group %0;" :: "n"(N));
}
__device__ __forceinline__ void ldsm4(uint32_t* r, uint32_t addr) {
    asm volatile("ldmatrix.sync.aligned.m8n8.x4.shared.b16 {%0,%1,%2,%3}, [%4];"
                 : "=r"(r[0]), "=r"(r[1]), "=r"(r[2]), "=r"(r[3]) : "r"(addr));
}
__device__ __forceinline__ void mma16816(float* c, const uint32_t* a,
                                         const uint32_t* b) {
    asm volatile(
        "mma.sync.aligned.m16n8k16.row.col.f32.f16.f16.f32 "
        "{%0,%1,%2,%3}, {%4,%5,%6,%7}, {%8,%9}, {%0,%1,%2,%3};"
        : "+f"(c[0]), "+f"(c[1]), "+f"(c[2]), "+f"(c[3])
        : "r"(a[0]), "r"(a[1]), "r"(a[2]), "r"(a[3]), "r"(b[0]), "r"(b[1]));
}

// ---------------- fp16 2-pass GEMM on mma.sync ----------------
// C[M,N] = (Ah+Al)[M,K] * Bh[N,K]^T, fp32 accum; error ~2^-13 (B rounding only).
// 128x128 CTA tile, K-chunk 64, 2-stage cp.async double buffer, ldmatrix feeds.
// smem tile layout: row r (128B) with 16B granule c stored at (c ^ (r&7)).
// Stage = {Ah 16KB, Al 16KB, Bh 16KB} = 48KB; 2 stages = 96KB.
#define HGE_STAGE 49152
#define HGE_SMEM  (2 * HGE_STAGE)

__device__ __forceinline__ void hge_load_chunk(const __half* Ah, const __half* Al,
                                               const __half* Bh, int bm, int bn,
                                               int K, int chunk, int s, int tid,
                                               uint32_t sb) {
    int kb = chunk << 6;
    uint32_t st = sb + (uint32_t)(s * HGE_STAGE);
    {   // A: threads 0..127 -> Ah row tid; 128..255 -> Al row tid-128
        const __half* asrc = (tid < 128) ? Ah : Al;
        int r = tid & 127;
        const char* g = (const char*)(asrc + (size_t)(bm + r) * K + kb);
        uint32_t d0 = st + ((tid >> 7) ? 16384u : 0u) + (uint32_t)(r << 7);
        int x = r & 7;
#pragma unroll
        for (int c = 0; c < 8; c++) cpa16(d0 + (uint32_t)((c ^ x) << 4), g + (c << 4));
    }
    {   // Bh: all 256 threads, 4 granules each (half a row)
        int g0 = tid << 2;
        int r = g0 >> 3, c0 = g0 & 7;
        const char* g = (const char*)(Bh + (size_t)(bn + r) * K + kb) + (c0 << 4);
        uint32_t d0 = st + 32768u + (uint32_t)(r << 7);
        int x = r & 7;
#pragma unroll
        for (int c = 0; c < 4; c++)
            cpa16(d0 + (uint32_t)(((c0 + c) ^ x) << 4), g + (c << 4));
    }
    cpa_commit();
}

__global__ __launch_bounds__(256, 1) void hf_gemm(
    const __half* __restrict__ Ah, const __half* __restrict__ Al,
    const __half* __restrict__ Bh, float* __restrict__ C, int M, int N, int K) {
    extern __shared__ __align__(128) char smem[];
    uint32_t sb = s2u(smem);
    int tid = threadIdx.x, lane = tid & 31, warp = tid >> 5;
    int bm = blockIdx.x << 7, bn = blockIdx.y << 7;   // x = M (fast) => B-panel L2 reuse
    int wm = (warp >> 2) << 6, wn = (warp & 3) << 5;  // warp tile 64x32
    int nk = K >> 6;

    float acc[4][4][4];
#pragma unroll
    for (int mt = 0; mt < 4; mt++)
#pragma unroll
        for (int nt = 0; nt < 4; nt++)
#pragma unroll
            for (int e = 0; e < 4; e++) acc[mt][nt][e] = 0.f;

    hge_load_chunk(Ah, Al, Bh, bm, bn, K, 0, 0, tid, sb);
    hge_load_chunk(Ah, Al, Bh, bm, bn, K, 1, 1, tid, sb);

    // per-thread ldmatrix row/granule components
    uint32_t a_row = (uint32_t)(wm + (lane & 15)) << 7;
    uint32_t b_row = (uint32_t)(wn + (lane & 7) + ((lane >> 4) << 3)) << 7;
    int ga = lane >> 4;          // A granule low bit
    int gb = (lane >> 3) & 1;    // B granule low bit
    int lx = lane & 7;

    for (int i = 0; i < nk; i++) {
        int s = i & 1;
        if (i + 1 < nk) cpa_wait<1>(); else cpa_wait<0>();
        __syncthreads();
        uint32_t st = sb + (uint32_t)(s * HGE_STAGE);
        uint32_t Ahb = st, Alb = st + 16384, Bhb = st + 32768;
#pragma unroll
        for (int kk = 0; kk < 4; kk++) {
            uint32_t xga = (uint32_t)((((kk << 1) + ga) ^ lx)) << 4;
            uint32_t xgb = (uint32_t)((((kk << 1) + gb) ^ lx)) << 4;
            uint32_t ahf[4][4], alf[4][4], bhf[2][4];
#pragma unroll
            for (int mt = 0; mt < 4; mt++) {
                ldsm4(ahf[mt], Ahb + a_row + (mt << 11) + xga);
                ldsm4(alf[mt], Alb + a_row + (mt << 11) + xga);
            }
#pragma unroll
            for (int nt = 0; nt < 2; nt++) ldsm4(bhf[nt], Bhb + b_row + (nt << 11) + xgb);
#pragma unroll
            for (int mt = 0; mt < 4; mt++)
#pragma unroll
                for (int nt = 0; nt < 4; nt++) {
                    const uint32_t* bh2 = &bhf[nt >> 1][(nt & 1) << 1];
                    mma16816(acc[mt][nt], ahf[mt], bh2);  // hi * Bh
                    mma16816(acc[mt][nt], alf[mt], bh2);  // lo * Bh
                }
        }
        __syncthreads();
        if (i + 2 < nk) hge_load_chunk(Ah, Al, Bh, bm, bn, K, i + 2, s, tid, sb);
    }

    // epilogue
    int r0 = bm + wm + (lane >> 2);
    int c0 = bn + wn + ((lane & 3) << 1);
#pragma unroll
    for (int mt = 0; mt < 4; mt++)
#pragma unroll
        for (int nt = 0; nt < 4; nt++) {
            float2 v0 = make_float2(acc[mt][nt][0], acc[mt][nt][1]);
            float2 v1 = make_float2(acc[mt][nt][2], acc[mt][nt][3]);
            *(float2*)&C[(size_t)(r0 + (mt << 4)) * N + c0 + (nt << 3)] = v0;
            *(float2*)&C[(size_t)(r0 + (mt << 4) + 8) * N + c0 + (nt << 3)] = v1;
        }
}

// ---------------- transpose + fp32 -> fp16 (hi only, weights) ----------------
__global__ __launch_bounds__(256) void transpose_conv(const float* __restrict__ in,
                                                      int R, int C,
                                                      __half* __restrict__ oh,
                                                      int ldo, int coff) {
    __shared__ float tbuf[32][33];
    int bc = blockIdx.x << 5, br = blockIdx.y << 5;
    int tx = threadIdx.x & 31, ty = threadIdx.x >> 5;
#pragma unroll
    for (int i = 0; i < 32; i += 8)
        tbuf[ty + i][tx] = in[(size_t)(br + ty + i) * C + bc + tx];
    __syncthreads();
#pragma unroll
    for (int i = 0; i < 32; i += 8) {
        float v = tbuf[tx][ty + i];
        size_t o = (size_t)(bc + ty + i) * ldo + coff + br + tx;
        oh[o] = __float2half_rn(v);
    }
}

// ---------------- LayerNorm -> fp16 hi/lo ----------------
__global__ __launch_bounds__(256) void ln_kernel(const float* __restrict__ x,
                                                 const float* __restrict__ gamma,
                                                 const float* __restrict__ beta) {
    int row = blockIdx.x;
    int tid = threadIdx.x;
    const float* xr = x + (size_t)row * DIMM;
    float v[8];
    float s = 0.f, s2 = 0.f;
#pragma unroll
    for (int i = 0; i < 8; i++) {
        float tv = xr[tid + i * 256];
        v[i] = tv; s += tv; s2 += tv * tv;
    }
#pragma unroll
    for (int o = 16; o > 0; o >>= 1) {
        s  += __shfl_xor_sync(0xffffffffu, s,  o);
        s2 += __shfl_xor_sync(0xffffffffu, s2, o);
    }
    __shared__ float rs[8], rs2[8];
    int w = tid >> 5, l = tid & 31;
    if (l == 0) { rs[w] = s; rs2[w] = s2; }
    __syncthreads();
    float S = 0.f, S2 = 0.f;
#pragma unroll
    for (int i = 0; i < 8; i++) { S += rs[i]; S2 += rs2[i]; }
    float mean = S * (1.f / DIMM);
    float var  = S2 * (1.f / DIMM) - mean * mean;
    float r = rsqrtf(var + 1e-5f);
    __half* hh = g_hh + (size_t)row * DIMM;
    __half* hl = g_hl + (size_t)row * DIMM;
#pragma unroll
    for (int i = 0; i < 8; i++) {
        int c = tid + i * 256;
        float y = (v[i] - mean) * r * gamma[c] + beta[c];
        __half hi = __float2half_rn(y);
        hh[c] = hi;
        hl[c] = __float2half_rn(y - __half2float(hi));
    }
}

// ---------------- RoPE ----------------
__global__ void rope_table_kernel() {
    int idx = blockIdx.x * blockDim.x + threadIdx.x;
    if (idx >= NSEQ * 64) return;
    int n = idx >> 6, i = idx & 63;
    double invf = pow(10000.0, -(double)i / 64.0);
    double th = (double)n * invf;
    g_cos[idx] = (float)cos(th);
    g_sin[idx] = (float)sin(th);
}

__global__ void rope_kernel() {
    int idx = blockIdx.x * blockDim.x + threadIdx.x;
    if (idx >= TOK * 17 * 64) return;
    int i = idx & 63;
    int t = idx >> 6;
    int head = t % 17;          // heads 0..15 = q, 16 = k
    int row = t / 17;
    int pos = row & (NSEQ - 1);
    float c = g_cos[(pos << 6) + i];
    float s = g_sin[(pos << 6) + i];
    size_t base = (size_t)row * FUSED + (head < 16 ? (head << 7) : 2048);
    float v0 = g_proj[base + i];
    float v1 = g_proj[base + i + 64];
    g_proj[base + i]      = v0 * c - v1 * s;
    g_proj[base + i + 64] = v1 * c + v0 * s;
}

// ---------------- fp32 flash attention (MQA, causal) -> fp16 hi/lo into a2 ----
#define ATTN_SMEM ((3 * 64 * 132 + 64 * 68) * 4)

__global__ __launch_bounds__(256, 1) void attn_kernel() {
    extern __shared__ float sm[];
    float* Qs = sm;                  // [64][132]
    float* Ks = sm + 64 * 132;
    float* Vs = sm + 2 * 64 * 132;
    float* Ps = sm + 3 * 64 * 132;   // [64][68]
    int tid = threadIdx.x;
    int qb = blockIdx.x, hh = blockIdx.y, bb = blockIdx.z;
    int row = tid >> 2, part = tid & 3;
    size_t rowbase = (size_t)(bb * NSEQ) * FUSED;

#pragma unroll
    for (int i = 0; i < 8; i++) {
        int f = tid + (i << 8);
        int r = f >> 5, c4 = (f & 31) << 2;
        *(float4*)&Qs[r * 132 + c4] =
            *(const float4*)(g_proj + rowbase + (size_t)(qb * 64 + r) * FUSED + hh * DH + c4);
    }

    float m_i = -1e30f, l_i = 0.f;
    float4 Oa[8];
#pragma unroll
    for (int j = 0; j < 8; j++) Oa[j] = make_float4(0.f, 0.f, 0.f, 0.f);
    const float scale = 0.08838834764831845f;
    int qg = qb * 64 + row;

    for (int kb = 0; kb <= qb; kb++) {
        __syncthreads();
#pragma unroll
        for (int i = 0; i < 8; i++) {
            int f = tid + (i << 8);
            int r = f >> 5, c4 = (f & 31) << 2;
            size_t src = rowbase + (size_t)(kb * 64 + r) * FUSED;
            *(float4*)&Ks[r * 132 + c4] = *(const float4*)(g_proj + src + 2048 + c4);
            *(float4*)&Vs[r * 132 + c4] = *(const float4*)(g_proj + src + 2176 + c4);
        }
        __syncthreads();

        float S[16];
#pragma unroll
        for (int j = 0; j < 16; j++) S[j] = 0.f;
#pragma unroll 4
        for (int k4 = 0; k4 < 128; k4 += 4) {
            float4 q = *(float4*)&Qs[row * 132 + k4];
#pragma unroll
            for (int j = 0; j < 16; j++) {
                float4 kv = *(float4*)&Ks[(part + (j << 2)) * 132 + k4];
                S[j] += q.x * kv.x + q.y * kv.y + q.z * kv.z + q.w * kv.w;
            }
        }
        float mx = -1e30f;
#pragma unroll
        for (int j = 0; j < 16; j++) {
            int kg = kb * 64 + part + (j << 2);
            S[j] = (kg <= qg) ? S[j] * scale : -1e30f;
            mx = fmaxf(mx, S[j]);
        }
        mx = fmaxf(mx, __shfl_xor_sync(0xffffffffu, mx, 1));
        mx = fmaxf(mx, __shfl_xor_sync(0xffffffffu, mx, 2));
        float m_new = fmaxf(m_i, mx);
        float alpha = __expf(m_i - m_new);
        float ps = 0.f;
#pragma unroll
        for (int j = 0; j < 16; j++) {
            float p = __expf(S[j] - m_new);
            S[j] = p; ps += p;
        }
        ps += __shfl_xor_sync(0xffffffffu, ps, 1);
        ps += __shfl_xor_sync(0xffffffffu, ps, 2);
        l_i = l_i * alpha + ps;
        m_i = m_new;
#pragma unroll
        for (int j = 0; j < 8; j++) {
            Oa[j].x *= alpha; Oa[j].y *= alpha; Oa[j].z *= alpha; Oa[j].w *= alpha;
        }
#pragma unroll
        for (int j = 0; j < 16; j++) Ps[row * 68 + part + (j << 2)] = S[j];
        __syncwarp();
#pragma unroll 4
        for (int c = 0; c < 64; c++) {
            float p = Ps[row * 68 + c];
            const float4* vr = (const float4*)&Vs[c * 132];
#pragma unroll
            for (int j = 0; j < 8; j++) {
                float4 v = vr[part + (j << 2)];
                Oa[j].x += p * v.x; Oa[j].y += p * v.y;
                Oa[j].z += p * v.z; Oa[j].w += p * v.w;
            }
        }
    }
    float inv = 1.f / l_i;
    size_t ob = (size_t)(bb * NSEQ + qb * 64 + row) * K2 + FFI + hh * DH;
#pragma unroll
    for (int j = 0; j < 8; j++) {
        int d = (part + (j << 2)) << 2;
        float vv[4] = {Oa[j].x * inv, Oa[j].y * inv, Oa[j].z * inv, Oa[j].w * inv};
#pragma unroll
        for (int e = 0; e < 4; e++) {
            __half hi = __float2half_rn(vv[e]);
            g_a2h[ob + d + e] = hi;
            g_a2l[ob + d + e] = __float2half_rn(vv[e] - __half2float(hi));
        }
    }
}

// ---------------- SwiGLU -> fp16 hi/lo into a2 ----------------
__global__ __launch_bounds__(256) void swiglu_kernel() {
    int idx = blockIdx.x * blockDim.x + threadIdx.x;
    if (idx >= TOK * (FFI / 4)) return;
    int row = idx / (FFI / 4);
    int c4 = (idx % (FFI / 4)) << 2;
    const float4 xv = *(const float4*)(g_proj + (size_t)row * FUSED + 2304 + c4);
    const float4 gv = *(const float4*)(g_proj + (size_t)row * FUSED + 2304 + FFI + c4);
    float o[4];
    o[0] = xv.x * gv.x / (1.f + __expf(-gv.x));
    o[1] = xv.y * gv.y / (1.f + __expf(-gv.y));
    o[2] = xv.z * gv.z / (1.f + __expf(-gv.z));
    o[3] = xv.w * gv.w / (1.f + __expf(-gv.w));
    size_t ob = (size_t)row * K2 + c4;
#pragma unroll
    for (int e = 0; e < 4; e++) {
        __half hi = __float2half_rn(o[e]);
        g_a2h[ob + e] = hi;
        g_a2l[ob + e] = __float2half_rn(o[e] - __half2float(hi));
    }
}

// ---------------- launch ----------------
extern "C" void kernel_launch(void* const* d_in, const int* in_sizes, int n_in,
                              void* d_out, int out_size) {
    (void)in_sizes; (void)n_in; (void)out_size;
    const float* x     = (const float*)d_in[0];
    const float* gamma = (const float*)d_in[1];
    const float* beta  = (const float*)d_in[2];
    const float* wf    = (const float*)d_in[3];
    const float* wao   = (const float*)d_in[4];
    const float* wfo   = (const float*)d_in[5];
    float* out = (float*)d_out;

    __half *phh, *phl, *pwfTh, *pw2Th, *pa2h, *pa2l;
    float* pproj;
    cudaGetSymbolAddress((void**)&pproj, g_proj);
    cudaGetSymbolAddress((void**)&phh, g_hh);
    cudaGetSymbolAddress((void**)&phl, g_hl);
    cudaGetSymbolAddress((void**)&pwfTh, g_wfTh);
    cudaGetSymbolAddress((void**)&pw2Th, g_w2Th);
    cudaGetSymbolAddress((void**)&pa2h, g_a2h);
    cudaGetSymbolAddress((void**)&pa2l, g_a2l);

    cudaFuncSetAttribute(hf_gemm, cudaFuncAttributeMaxDynamicSharedMemorySize,
                         HGE_SMEM);
    cudaFuncSetAttribute(attn_kernel, cudaFuncAttributeMaxDynamicSharedMemorySize,
                         ATTN_SMEM);

    // weight conversions (transposed fp16 hi)
    transpose_conv<<<dim3(FUSED / 32, DIMM / 32), 256>>>(wf, DIMM, FUSED,
                                                         pwfTh, DIMM, 0);
    transpose_conv<<<dim3(DIMM / 32, FFI / 32), 256>>>(wfo, FFI, DIMM,
                                                       pw2Th, K2, 0);
    transpose_conv<<<dim3(DIMM / 32, DIMM / 32), 256>>>(wao, DIMM, DIMM,
                                                        pw2Th, K2, FFI);
    // LayerNorm
    ln_kernel<<<TOK, 256>>>(x, gamma, beta);
    // fused projection GEMM: [4096,2048] x [18688,2048]^T -> g_proj
    hf_gemm<<<dim3(TOK / 128, FUSED / 128), 256, HGE_SMEM>>>(
        phh, phl, pwfTh, pproj, TOK, FUSED, DIMM);
    // RoPE
    rope_table_kernel<<<(NSEQ * 64 + 255) / 256, 256>>>();
    rope_kernel<<<(TOK * 17 * 64 + 255) / 256, 256>>>();
    // attention -> a2[:, 8192:]
    attn_kernel<<<dim3(QB, 16, 2), 256, ATTN_SMEM>>>();
    // swiglu -> a2[:, :8192]
    swiglu_kernel<<<(TOK * (FFI / 4) + 255) / 256, 256>>>();
    // combined output GEMM: [4096,10240] x [2048,10240]^T -> out
    hf_gemm<<<dim3(TOK / 128, DIMM / 128), 256, HGE_SMEM>>>(
        pa2h, pa2l, pw2Th, out, TOK, DIMM, K2);
}